// round 11
// baseline (speedup 1.0000x reference)
#include <cuda_runtime.h>
#include <cstdint>

// Problem constants (from reference)
#define PCR0      (-51.2f)
#define VX        (0.05f)
#define STRIDE_F  (4.0f)
#define FW        512
#define FH        512
#define NUM_CLASSES 10
#define NUM_MAX_OBJS 500
#define BATCH     16
#define OVERLAP   (0.1f)
#define MIN_RADIUS 2
#define RMAX      16

#define HEAT_ELEMS   ((size_t)BATCH * NUM_CLASSES * FH * FW)
#define BOXES_ELEMS  ((size_t)BATCH * NUM_MAX_OBJS * 8)
#define INDS_ELEMS   ((size_t)BATCH * NUM_MAX_OBJS)

#define TOBJ   (BATCH * NUM_MAX_OBJS)      // 8000
#define NTX    8                            // 512/64 tiles per row
#define TILES_PER_PLANE 64
#define NTILE  (BATCH * NUM_CLASSES * TILES_PER_PLANE)  // 10240
#define CAP    32

#define NBIN_BLOCKS 32                      // ceil(8000 / 256)
#define GRID_TOTAL  (NBIN_BLOCKS + NTILE)

// Static device scratch. All start zeroed (static init) and are restored to
// zero by the kernel itself before it exits -> deterministic graph replays.
__device__ int  d_cnt     [NTILE];
__device__ int4 d_tilemeta[NTILE * CAP];   // {cxi, cyi, r, bits(-1/(2 sigma^2))}
__device__ int  d_done;                    // bin blocks completed
__device__ int  d_fin;                     // gather blocks completed

__device__ __forceinline__ float gaussian_radius(float h, float w, float ov) {
    float b1 = h + w;
    float c1 = w * h * (1.0f - ov) / (1.0f + ov);
    float sq1 = sqrtf(fmaxf(b1 * b1 - 4.0f * c1, 0.0f));
    float r1 = (b1 + sq1) * 0.5f;

    float b2 = 2.0f * (h + w);
    float c2 = (1.0f - ov) * w * h;
    float sq2 = sqrtf(fmaxf(b2 * b2 - 16.0f * c2, 0.0f));
    float r2 = (b2 + sq2) * 0.5f;

    float a3 = 4.0f * ov;
    float b3 = -2.0f * ov * (h + w);
    float c3 = (ov - 1.0f) * w * h;
    float sq3 = sqrtf(fmaxf(b3 * b3 - 4.0f * a3 * c3, 0.0f));
    float r3 = (b3 + sq3) / (2.0f * a3);

    return fminf(fminf(r1, r2), r3);
}

// Fused kernel. Blocks 0..NBIN_BLOCKS-1: per-object binning + per-object
// outputs, then arrive on d_done. Remaining NTILE blocks: wait for all bin
// blocks, then gather one 64x64 tile (stores double as the zero-fill).
// Deadlock-safe: bin blocks have the lowest bids -> scheduled in wave 1.
__global__ void __launch_bounds__(256, 8) fused_kernel(
        const float* __restrict__ gt,
        float* __restrict__ heat,
        float* __restrict__ boxes,
        float* __restrict__ inds,
        float* __restrict__ mask)
{
    const int tid = threadIdx.x;

    if (blockIdx.x < NBIN_BLOCKS) {
        // ---------------- bin phase ----------------
        const int obj = blockIdx.x * 256 + tid;
        if (obj < TOBJ) {
            const int b = obj / NUM_MAX_OBJS;

            const float4 g0 = __ldg((const float4*)(gt + (size_t)obj * 8));
            const float4 g1 = __ldg((const float4*)(gt + (size_t)obj * 8) + 1);
            const float x  = g0.x, y  = g0.y, z = g0.z, dx = g0.w;
            const float dy = g1.x, dz = g1.y, hd = g1.z;
            const int   cls = (int)(g1.w - 1.0f);

            float coord_x = (x - PCR0) / VX / STRIDE_F;
            float coord_y = (y - PCR0) / VX / STRIDE_F;
            coord_x = fminf(fmaxf(coord_x, 0.0f), (float)FW - 0.5f);
            coord_y = fminf(fmaxf(coord_y, 0.0f), (float)FH - 0.5f);
            const int cxi = (int)coord_x;
            const int cyi = (int)coord_y;

            const float dxf = dx / VX / STRIDE_F;
            const float dyf = dy / VX / STRIDE_F;

            int r = (int)gaussian_radius(dxf, dyf, OVERLAP);
            r = min(max(r, MIN_RADIUS), RMAX);

            const bool valid = (dxf > 0.0f) && (dyf > 0.0f) &&
                               (cxi >= 0) && (cxi <= FW) &&
                               (cyi >= 0) && (cyi <= FH);

            {
                const float vf = valid ? 1.0f : 0.0f;
                float* bo = boxes + (size_t)obj * 8;
                bo[0] = (coord_x - (float)cxi) * vf;
                bo[1] = (coord_y - (float)cyi) * vf;
                bo[2] = z * vf;
                bo[3] = __logf(fmaxf(dx, 1e-12f)) * vf;
                bo[4] = __logf(fmaxf(dy, 1e-12f)) * vf;
                bo[5] = __logf(fmaxf(dz, 1e-12f)) * vf;
                bo[6] = __cosf(hd) * vf;
                bo[7] = __sinf(hd) * vf;
                inds[obj] = valid ? (float)(cyi * FW + cxi) : 0.0f;
                mask[obj] = vf;
            }

            if (valid) {
                const float sigma   = (2.0f * (float)r + 1.0f) / 6.0f;
                const float ninv2s2 = -1.0f / (2.0f * sigma * sigma);
                const int4 meta = make_int4(cxi, cyi, r, __float_as_int(ninv2s2));

                const int c = min(max(cls, 0), NUM_CLASSES - 1);
                const int ty0 = max(cyi - r, 0) >> 6;
                const int ty1 = min(cyi + r, FH - 1) >> 6;
                const int tx0 = max(cxi - r, 0) >> 6;
                const int tx1 = min(cxi + r, FW - 1) >> 6;
                const int pbase = (b * NUM_CLASSES + c) * TILES_PER_PLANE;
                for (int ty = ty0; ty <= ty1; ty++)
                    for (int tx = tx0; tx <= tx1; tx++) {
                        const int t = pbase + ty * NTX + tx;
                        const int idx = atomicAdd(&d_cnt[t], 1);
                        if (idx < CAP) d_tilemeta[t * CAP + idx] = meta;
                    }
            }
        }
        // Publish: all this block's meta/cnt writes, then arrive.
        __threadfence();
        __syncthreads();
        if (tid == 0) atomicAdd(&d_done, 1);
        return;
    }

    // ---------------- gather phase ----------------
    const int blk  = blockIdx.x - NBIN_BLOCKS;
    const int tile = blk & (TILES_PER_PLANE - 1);
    const int pc   = blk >> 6;                 // b*NUM_CLASSES + c
    const int tx   = tile & (NTX - 1);
    const int ty   = tile >> 3;

    const int x0   = (tx << 6) + ((tid & 15) << 2);   // fixed 4-px strip
    const int r0   = (ty << 6) + (tid >> 4);          // rows r0 + q*16

    // Wait for all bin blocks (1 polling thread, then block barrier).
    if (tid == 0) {
        while (*(volatile int*)&d_done < NBIN_BLOCKS)
            __nanosleep(64);
    }
    __syncthreads();
    __threadfence();   // acquire: order subsequent reads after the flag

    const int n = min(d_cnt[blk], CAP);

    float acc[4][4];
    #pragma unroll
    for (int q = 0; q < 4; q++)
        #pragma unroll
        for (int k = 0; k < 4; k++) acc[q][k] = 0.0f;

    for (int i = 0; i < n; i++) {
        const int4 m = __ldg(&d_tilemeta[blk * CAP + i]);  // cx, cy, r, a
        const int d0 = x0 - m.x;
        if (d0 > m.z || d0 + 3 < -m.z) continue;           // column strip reject
        const float a = __int_as_float(m.w);               // -1/(2 sigma^2)

        float fj[4];
        #pragma unroll
        for (int k = 0; k < 4; k++) {
            const int adx = abs(d0 + k);
            const float e = __expf((float)(adx * adx) * a);
            fj[k] = (adx <= m.z) ? e : 0.0f;
        }

        #pragma unroll
        for (int q = 0; q < 4; q++) {
            const int ady = abs(r0 + q * 16 - m.y);
            if (ady > m.z) continue;
            const float fi = __expf((float)(ady * ady) * a);
            #pragma unroll
            for (int k = 0; k < 4; k++)
                acc[q][k] = fmaxf(acc[q][k], fi * fj[k]);
        }
    }

    float* base = heat + ((size_t)pc * FH) * FW;
    #pragma unroll
    for (int q = 0; q < 4; q++)
        *(float4*)(base + (size_t)(r0 + q * 16) * FW + x0) =
            make_float4(acc[q][0], acc[q][1], acc[q][2], acc[q][3]);

    // Self-clean for the next replay. Barrier orders the resets after every
    // thread's d_cnt/meta reads; the LAST gather block resets the flags.
    __syncthreads();
    if (tid == 0) {
        d_cnt[blk] = 0;
        const int f = atomicAdd(&d_fin, 1);
        if (f == NTILE - 1) {          // last gather block on this replay
            atomicExch(&d_fin, 0);
            atomicExch(&d_done, 0);
        }
    }
}

extern "C" void kernel_launch(void* const* d_in, const int* in_sizes, int n_in,
                              void* d_out, int out_size) {
    const float* gt = (const float*)d_in[0];
    float* out = (float*)d_out;

    float* heat  = out;
    float* boxes = out + HEAT_ELEMS;
    float* inds  = out + HEAT_ELEMS + BOXES_ELEMS;
    float* mask  = out + HEAT_ELEMS + BOXES_ELEMS + INDS_ELEMS;

    fused_kernel<<<GRID_TOTAL, 256>>>(gt, heat, boxes, inds, mask);
}

// round 12
// speedup vs baseline: 1.2873x; 1.2873x over previous
#include <cuda_runtime.h>
#include <cstdint>

// Problem constants (from reference)
#define PCR0      (-51.2f)
#define VX        (0.05f)
#define STRIDE_F  (4.0f)
#define FW        512
#define FH        512
#define NUM_CLASSES 10
#define NUM_MAX_OBJS 500
#define BATCH     16
#define OVERLAP   (0.1f)
#define MIN_RADIUS 2
#define RMAX      16

#define HEAT_ELEMS   ((size_t)BATCH * NUM_CLASSES * FH * FW)
#define BOXES_ELEMS  ((size_t)BATCH * NUM_MAX_OBJS * 8)
#define INDS_ELEMS   ((size_t)BATCH * NUM_MAX_OBJS)

#define TOBJ   (BATCH * NUM_MAX_OBJS)      // 8000
#define NTX    8                            // 512/64 tiles per row
#define TILES_PER_PLANE 64
#define NTILE  (BATCH * NUM_CLASSES * TILES_PER_PLANE)  // 10240
#define CAP    32

// Static device scratch. d_cnt starts zeroed (static init) and is
// self-cleaned at the end of gather_kernel -> deterministic graph replays.
__device__ int  d_cnt     [NTILE];
__device__ int4 d_tilemeta[NTILE * CAP];   // {cxi, cyi, r, bits(-1/(2 sigma^2))}

__device__ __forceinline__ float gaussian_radius(float h, float w, float ov) {
    float b1 = h + w;
    float c1 = w * h * (1.0f - ov) / (1.0f + ov);
    float sq1 = sqrtf(fmaxf(b1 * b1 - 4.0f * c1, 0.0f));
    float r1 = (b1 + sq1) * 0.5f;

    float b2 = 2.0f * (h + w);
    float c2 = (1.0f - ov) * w * h;
    float sq2 = sqrtf(fmaxf(b2 * b2 - 16.0f * c2, 0.0f));
    float r2 = (b2 + sq2) * 0.5f;

    float a3 = 4.0f * ov;
    float b3 = -2.0f * ov * (h + w);
    float c3 = (ov - 1.0f) * w * h;
    float sq3 = sqrtf(fmaxf(b3 * b3 - 4.0f * a3 * c3, 0.0f));
    float r3 = (b3 + sq3) / (2.0f * a3);

    return fminf(fminf(r1, r2), r3);
}

// One thread per object: per-object outputs + one int4 per intersecting tile.
__global__ void __launch_bounds__(64) bin_kernel(
        const float* __restrict__ gt,
        float* __restrict__ boxes,
        float* __restrict__ inds,
        float* __restrict__ mask)
{
    const int obj = blockIdx.x * blockDim.x + threadIdx.x;
    if (obj >= TOBJ) return;
    const int b = obj / NUM_MAX_OBJS;

    const float4 g0 = __ldg((const float4*)(gt + (size_t)obj * 8));
    const float4 g1 = __ldg((const float4*)(gt + (size_t)obj * 8) + 1);
    const float x  = g0.x, y  = g0.y, z = g0.z, dx = g0.w;
    const float dy = g1.x, dz = g1.y, hd = g1.z;
    const int   cls = (int)(g1.w - 1.0f);

    float coord_x = (x - PCR0) / VX / STRIDE_F;
    float coord_y = (y - PCR0) / VX / STRIDE_F;
    coord_x = fminf(fmaxf(coord_x, 0.0f), (float)FW - 0.5f);
    coord_y = fminf(fmaxf(coord_y, 0.0f), (float)FH - 0.5f);
    const int cxi = (int)coord_x;
    const int cyi = (int)coord_y;

    const float dxf = dx / VX / STRIDE_F;
    const float dyf = dy / VX / STRIDE_F;

    int r = (int)gaussian_radius(dxf, dyf, OVERLAP);
    r = min(max(r, MIN_RADIUS), RMAX);

    const bool valid = (dxf > 0.0f) && (dyf > 0.0f) &&
                       (cxi >= 0) && (cxi <= FW) &&
                       (cyi >= 0) && (cyi <= FH);

    {
        const float vf = valid ? 1.0f : 0.0f;
        float* bo = boxes + (size_t)obj * 8;
        bo[0] = (coord_x - (float)cxi) * vf;
        bo[1] = (coord_y - (float)cyi) * vf;
        bo[2] = z * vf;
        bo[3] = __logf(fmaxf(dx, 1e-12f)) * vf;
        bo[4] = __logf(fmaxf(dy, 1e-12f)) * vf;
        bo[5] = __logf(fmaxf(dz, 1e-12f)) * vf;
        bo[6] = __cosf(hd) * vf;
        bo[7] = __sinf(hd) * vf;
        inds[obj] = valid ? (float)(cyi * FW + cxi) : 0.0f;
        mask[obj] = vf;
    }

    if (!valid) return;

    const float sigma   = (2.0f * (float)r + 1.0f) / 6.0f;
    const float ninv2s2 = -1.0f / (2.0f * sigma * sigma);
    const int4 meta = make_int4(cxi, cyi, r, __float_as_int(ninv2s2));

    const int c = min(max(cls, 0), NUM_CLASSES - 1);
    const int ty0 = max(cyi - r, 0) >> 6;
    const int ty1 = min(cyi + r, FH - 1) >> 6;
    const int tx0 = max(cxi - r, 0) >> 6;
    const int tx1 = min(cxi + r, FW - 1) >> 6;
    const int pbase = (b * NUM_CLASSES + c) * TILES_PER_PLANE;
    for (int ty = ty0; ty <= ty1; ty++)
        for (int tx = tx0; tx <= tx1; tx++) {
            const int t = pbase + ty * NTX + tx;
            const int idx = atomicAdd(&d_cnt[t], 1);
            if (idx < CAP) d_tilemeta[t * CAP + idx] = meta;
        }
}

// One 256-thread block per 64x64 tile. Launched with PDL: blocks start while
// bin_kernel drains, do their index math, then hardware-wait for bin's
// completion before touching d_cnt/d_tilemeta.
__global__ void __launch_bounds__(256) gather_kernel(float* __restrict__ heat)
{
    const int blk  = blockIdx.x;
    const int tile = blk & (TILES_PER_PLANE - 1);
    const int pc   = blk >> 6;                 // b*NUM_CLASSES + c
    const int tx   = tile & (NTX - 1);
    const int ty   = tile >> 3;

    const int tid  = threadIdx.x;
    const int x0   = (tx << 6) + ((tid & 15) << 2);   // fixed 4-px strip
    const int r0   = (ty << 6) + (tid >> 4);          // rows r0 + q*16

    float acc[4][4];
    #pragma unroll
    for (int q = 0; q < 4; q++)
        #pragma unroll
        for (int k = 0; k < 4; k++) acc[q][k] = 0.0f;

    // HW wait for the primary (bin_kernel) to complete; all its global
    // writes are visible afterwards.
    cudaGridDependencySynchronize();

    const int n = min(d_cnt[blk], CAP);

    for (int i = 0; i < n; i++) {
        const int4 m = __ldg(&d_tilemeta[blk * CAP + i]);  // cx, cy, r, a
        const int d0 = x0 - m.x;
        if (d0 > m.z || d0 + 3 < -m.z) continue;           // column strip reject
        const float a = __int_as_float(m.w);               // -1/(2 sigma^2)

        float fj[4];
        #pragma unroll
        for (int k = 0; k < 4; k++) {
            const int adx = abs(d0 + k);
            const float e = __expf((float)(adx * adx) * a);
            fj[k] = (adx <= m.z) ? e : 0.0f;
        }

        #pragma unroll
        for (int q = 0; q < 4; q++) {
            const int ady = abs(r0 + q * 16 - m.y);
            if (ady > m.z) continue;
            const float fi = __expf((float)(ady * ady) * a);
            #pragma unroll
            for (int k = 0; k < 4; k++)
                acc[q][k] = fmaxf(acc[q][k], fi * fj[k]);
        }
    }

    float* base = heat + ((size_t)pc * FH) * FW;
    #pragma unroll
    for (int q = 0; q < 4; q++)
        *(float4*)(base + (size_t)(r0 + q * 16) * FW + x0) =
            make_float4(acc[q][0], acc[q][1], acc[q][2], acc[q][3]);

    // Self-clean the counter for the next replay; barrier orders the reset
    // after every thread's d_cnt read.
    __syncthreads();
    if (tid == 0) d_cnt[blk] = 0;
}

extern "C" void kernel_launch(void* const* d_in, const int* in_sizes, int n_in,
                              void* d_out, int out_size) {
    const float* gt = (const float*)d_in[0];
    float* out = (float*)d_out;

    float* heat  = out;
    float* boxes = out + HEAT_ELEMS;
    float* inds  = out + HEAT_ELEMS + BOXES_ELEMS;
    float* mask  = out + HEAT_ELEMS + BOXES_ELEMS + INDS_ELEMS;

    bin_kernel<<<(TOBJ + 63) / 64, 64>>>(gt, boxes, inds, mask);

    // Gather with Programmatic Dependent Launch: overlaps its launch/rollout
    // with bin_kernel's tail; cudaGridDependencySynchronize() inside gates
    // the actual data consumption.
    cudaLaunchConfig_t cfg = {};
    cfg.gridDim  = dim3(NTILE, 1, 1);
    cfg.blockDim = dim3(256, 1, 1);
    cfg.dynamicSmemBytes = 0;
    cfg.stream = 0;
    cudaLaunchAttribute attrs[1];
    attrs[0].id = cudaLaunchAttributeProgrammaticStreamSerialization;
    attrs[0].val.programmaticStreamSerializationAllowed = 1;
    cfg.attrs = attrs;
    cfg.numAttrs = 1;
    cudaLaunchKernelEx(&cfg, gather_kernel, heat);
}